// round 2
// baseline (speedup 1.0000x reference)
#include <cuda_runtime.h>
#include <math.h>

#define BATCH 4096
#define N_A0 (BATCH*196)        /* 802816  pooled input 14x14   */
#define N_Z1 (BATCH*64*144)     /* 37748736 conv1 out 12x12x64  */
#define N_Z2 (BATCH*16*100)     /* 6553600  conv2 out 10x10x16  */
#define N_P2 (BATCH*16*25)      /* 1638400  pooled 5x5x16       */
#define N_Y3 (BATCH*128)

__device__ float g_a0raw[N_A0];
__device__ float g_a0q[N_A0];
__device__ float g_z1[N_Z1];
__device__ float g_z2[N_Z2];
__device__ float g_p2[N_P2];
__device__ float g_y3[N_Y3];
__device__ float g_w1[576];
__device__ float g_w2[9216];
__device__ float g_w3[51200];
__device__ float g_w3t[51200];
__device__ float g_w4[1280];
__device__ float g_inv[4];
__device__ float g_bn1m[64], g_bn1i[64];
__device__ float g_bn2m[16], g_bn2i[16];
__device__ float g_part1[64*64*2];
__device__ float g_part2[16*16*2];
__device__ unsigned g_mm[8];   /* pairs: [min,max] encoded, slots 0..3 */

__device__ __forceinline__ unsigned fenc(float f){
    unsigned u = __float_as_uint(f);
    return (u & 0x80000000u) ? ~u : (u | 0x80000000u);
}
__device__ __forceinline__ float fdec(unsigned u){
    return (u & 0x80000000u) ? __uint_as_float(u & 0x7FFFFFFFu) : __uint_as_float(~u);
}

__global__ void k_init(){
    int t = threadIdx.x;
    if (t < 8) g_mm[t] = (t & 1) ? 0u : 0xFFFFFFFFu;
}

/* ---- maxpool 28->14 + global min/max of pooled tensor ---- */
__global__ void k_pool0(const float* __restrict__ x){
    __shared__ unsigned smn, smx;
    if (threadIdx.x == 0){ smn = 0xFFFFFFFFu; smx = 0u; }
    __syncthreads();
    unsigned lmn = 0xFFFFFFFFu, lmx = 0u;
    int stride = gridDim.x * blockDim.x;
    for (int o = blockIdx.x*blockDim.x + threadIdx.x; o < N_A0; o += stride){
        int b = o / 196, p = o % 196, r = p / 14, c = p % 14;
        const float* px = &x[b*784 + (r*2)*28 + c*2];
        float v = fmaxf(fmaxf(px[0], px[1]), fmaxf(px[28], px[29]));
        g_a0raw[o] = v;
        unsigned e = fenc(v);
        lmn = min(lmn, e); lmx = max(lmx, e);
    }
    atomicMin(&smn, lmn); atomicMax(&smx, lmx);
    __syncthreads();
    if (threadIdx.x == 0){ atomicMin(&g_mm[0], smn); atomicMax(&g_mm[1], smx); }
}

/* ---- input quantization (after_relu = False) ---- */
__global__ void k_quant0(const int* __restrict__ qb){
    float mn = fdec(g_mm[0]), mx = fdec(g_mm[1]);
    float lv = (float)((1 << qb[0]) - 1);
    float sc = (mx - mn) / lv;
    float zp = floorf(mn / sc);
    int stride = gridDim.x * blockDim.x;
    for (int o = blockIdx.x*blockDim.x + threadIdx.x; o < N_A0; o += stride){
        float v = g_a0raw[o];
        g_a0q[o] = (rintf((v - mn)/sc) + zp) * sc;
    }
}

/* ---- weight gen: mean(hw_one)->scale, exact top-half mask with stable-tie
        semantics (radix select on |score| bits + tie-index cutoff) ---- */
__global__ void k_wgen(const float* __restrict__ sc, const float* __restrict__ sg,
                       const float* __restrict__ h1, const float* __restrict__ h0,
                       int layer, int n, float coeff)
{
    float* w = (layer==0) ? g_w1 : (layer==1) ? g_w2 : (layer==2) ? g_w3 : g_w4;
    __shared__ float red[1024];
    __shared__ unsigned hist[256];
    __shared__ unsigned sh_pref;
    __shared__ int sh_rank;
    __shared__ int ties[2048];
    __shared__ int ntie, Gtot, Cidx;
    int t = threadIdx.x;

    float s = 0.f;
    for (int i = t; i < n; i += 1024) s += h1[i];
    red[t] = s; __syncthreads();
    for (int o = 512; o > 0; o >>= 1){ if (t < o) red[t] += red[t+o]; __syncthreads(); }
    if (t == 0) g_inv[layer] = coeff / (red[0] / (float)n);

    unsigned pref = 0; int rank = n >> 1;             /* rank j = n/2 (ascending) */
    for (int shift = 24; shift >= 0; shift -= 8){
        if (t < 256) hist[t] = 0;
        __syncthreads();
        unsigned mask = (shift < 24) ? (0xFFFFFFFFu << (shift+8)) : 0u;
        for (int i = t; i < n; i += 1024){
            unsigned k = __float_as_uint(fabsf(sc[i]));
            if ((k & mask) == (pref & mask)) atomicAdd(&hist[(k >> shift) & 255], 1u);
        }
        __syncthreads();
        if (t == 0){
            unsigned c = 0; int d = 0;
            for (; d < 255; d++){ if (c + hist[d] > (unsigned)rank) break; c += hist[d]; }
            sh_pref = pref | ((unsigned)d << shift);
            sh_rank = rank - (int)c;
        }
        __syncthreads();
        pref = sh_pref; rank = sh_rank;
        __syncthreads();
    }
    unsigned thr = pref;
    if (t == 0){ ntie = 0; Gtot = 0; }
    __syncthreads();
    int g = 0;
    for (int i = t; i < n; i += 1024){
        unsigned k = __float_as_uint(fabsf(sc[i]));
        if (k > thr) g++;
        else if (k == thr){ int p = atomicAdd(&ntie, 1); if (p < 2048) ties[p] = i; }
    }
    atomicAdd(&Gtot, g);
    __syncthreads();
    if (t == 0){
        int E = ntie; if (E > 2048) E = 2048;
        for (int a = 1; a < E; a++){            /* ascending insertion sort */
            int v = ties[a]; int b2 = a - 1;
            while (b2 >= 0 && ties[b2] > v){ ties[b2+1] = ties[b2]; b2--; }
            ties[b2+1] = v;
        }
        int T1 = (n - (n >> 1)) - Gtot;         /* ties that must get mask=1 */
        if (T1 < 1) T1 = 1; if (T1 > E) T1 = E;
        Cidx = ties[E - T1];
    }
    __syncthreads();
    int C = Cidx;
    for (int i = t; i < n; i += 1024){
        unsigned k = __float_as_uint(fabsf(sc[i]));
        bool m = (k > thr) || (k == thr && i >= C);
        w[i] = sg[i] * (m ? h1[i] : h0[i]);
    }
}

__global__ void k_transp3(){
    int i = blockIdx.x*blockDim.x + threadIdx.x;
    if (i < 51200){ int nn = i / 400, k = i % 400; g_w3t[k*128 + nn] = g_w3[i]; }
}

/* ---- conv1: [B,1,14,14] -> [B,64,12,12], /scale1 ---- */
__global__ void k_conv1(){
    __shared__ float in_s[196];
    __shared__ float ws[576];
    int b = blockIdx.x, t = threadIdx.x;
    for (int i = t; i < 196; i += 256) in_s[i] = g_a0q[b*196 + i];
    for (int i = t; i < 576; i += 256) ws[i] = g_w1[i];
    __syncthreads();
    float inv = g_inv[0];
    for (int o = t; o < 9216; o += 256){
        int co = o / 144, p = o % 144, ho = p / 12, wo = p % 12;
        const float* wr = &ws[co*9];
        float acc = 0.f;
        #pragma unroll
        for (int kh = 0; kh < 3; kh++)
            #pragma unroll
            for (int kw = 0; kw < 3; kw++)
                acc = fmaf(in_s[(ho+kh)*14 + wo+kw], wr[kh*3+kw], acc);
        g_z1[b*9216 + o] = acc * inv;
    }
}

/* ---- bn1 stats (deterministic two-stage) ---- */
__global__ void k_stats1(){
    int c = blockIdx.x, p = blockIdx.y, t = threadIdx.x;
    float s = 0.f, q = 0.f;
    for (int i = t; i < 64*144; i += 256){
        int bb = p*64 + i/144;
        float v = g_z1[(bb*64 + c)*144 + (i % 144)];
        s += v; q += v*v;
    }
    __shared__ float rs[256], rq[256];
    rs[t] = s; rq[t] = q; __syncthreads();
    for (int o = 128; o > 0; o >>= 1){ if (t < o){ rs[t]+=rs[t+o]; rq[t]+=rq[t+o]; } __syncthreads(); }
    if (t == 0){ g_part1[(c*64+p)*2] = rs[0]; g_part1[(c*64+p)*2+1] = rq[0]; }
}
__global__ void k_fin1(){
    int c = threadIdx.x; if (c >= 64) return;
    float s = 0.f, q = 0.f;
    for (int p = 0; p < 64; p++){ s += g_part1[(c*64+p)*2]; q += g_part1[(c*64+p)*2+1]; }
    float N = (float)(BATCH*144);
    float m = s / N; float v = q / N - m*m;
    g_bn1m[c] = m; g_bn1i[c] = 1.0f / sqrtf(v + 1e-5f);
}

/* ---- min/max of relu(bn1(z1)) ---- */
__global__ void k_mm1(){
    __shared__ unsigned smn, smx;
    if (threadIdx.x == 0){ smn = 0xFFFFFFFFu; smx = 0u; }
    __syncthreads();
    unsigned lmn = 0xFFFFFFFFu, lmx = 0u;
    int stride = gridDim.x * blockDim.x;
    for (int i4 = blockIdx.x*blockDim.x + threadIdx.x; i4 < N_Z1/4; i4 += stride){
        int i = i4 * 4;
        int c = (i / 144) % 64;
        float4 v = *(const float4*)&g_z1[i];
        float m = g_bn1m[c], is = g_bn1i[c];
        float y0 = fmaxf((v.x-m)*is, 0.f), y1 = fmaxf((v.y-m)*is, 0.f);
        float y2 = fmaxf((v.z-m)*is, 0.f), y3 = fmaxf((v.w-m)*is, 0.f);
        unsigned e0=fenc(y0), e1=fenc(y1), e2=fenc(y2), e3=fenc(y3);
        lmn = min(min(lmn,e0), min(min(e1,e2),e3));
        lmx = max(max(lmx,e0), max(max(e1,e2),e3));
    }
    atomicMin(&smn, lmn); atomicMax(&smx, lmx);
    __syncthreads();
    if (threadIdx.x == 0){ atomicMin(&g_mm[2], smn); atomicMax(&g_mm[3], smx); }
}

/* ---- conv2: bn1+relu+quant applied on load; [B,64,12,12]->[B,16,10,10] ---- */
__global__ void k_conv2(const int* __restrict__ qb){
    extern __shared__ float sm[];
    float* in_s = sm;               /* 64*12*13 */
    float* ws   = sm + 64*12*13;    /* 16*577   */
    int b = blockIdx.x, t = threadIdx.x;
    float mn = fdec(g_mm[2]), mx = fdec(g_mm[3]);
    float lv = (float)((1 << qb[0]) - 1);
    float qs = (mx - mn) / lv;
    for (int i = t; i < 9216; i += 160){
        int ci = i / 144, r = i % 144, h = r / 12, w = r % 12;
        float v = g_z1[b*9216 + i];
        float y = fmaxf((v - g_bn1m[ci]) * g_bn1i[ci], 0.f);
        float q = fminf(fmaxf(rintf(y/qs), 0.f), lv) * qs;
        in_s[(ci*12 + h)*13 + w] = q;
    }
    for (int i = t; i < 9216; i += 160){
        int co = i / 576, r = i % 576;
        ws[co*577 + r] = g_w2[i];
    }
    __syncthreads();
    int co = t / 10, ho = t % 10;
    float acc[10];
    #pragma unroll
    for (int i = 0; i < 10; i++) acc[i] = 0.f;
    for (int ci = 0; ci < 64; ci++){
        #pragma unroll
        for (int kh = 0; kh < 3; kh++){
            const float* wr = &ws[co*577 + ci*9 + kh*3];
            float w0 = wr[0], w1 = wr[1], w2 = wr[2];
            const float* ir = &in_s[(ci*12 + ho + kh)*13];
            float r[12];
            #pragma unroll
            for (int j = 0; j < 12; j++) r[j] = ir[j];
            #pragma unroll
            for (int wo = 0; wo < 10; wo++)
                acc[wo] = fmaf(r[wo], w0, fmaf(r[wo+1], w1, fmaf(r[wo+2], w2, acc[wo])));
        }
    }
    float inv = g_inv[1];
    int base = (b*16 + co)*100 + ho*10;
    #pragma unroll
    for (int wo = 0; wo < 10; wo++) g_z2[base + wo] = acc[wo] * inv;
}

/* ---- maxpool 10->5 ---- */
__global__ void k_pool2(){
    int stride = gridDim.x * blockDim.x;
    for (int o = blockIdx.x*blockDim.x + threadIdx.x; o < N_P2; o += stride){
        int b = o / 400, rem = o % 400, c = rem / 25, rr = rem % 25, i = rr/5, j = rr%5;
        const float* p = &g_z2[(b*16 + c)*100 + (2*i)*10 + 2*j];
        g_p2[o] = fmaxf(fmaxf(p[0], p[1]), fmaxf(p[10], p[11]));
    }
}

__global__ void k_stats2(){
    int c = blockIdx.x, p = blockIdx.y, t = threadIdx.x;
    float s = 0.f, q = 0.f;
    for (int i = t; i < 256*25; i += 256){
        int bb = p*256 + i/25;
        float v = g_p2[(bb*16 + c)*25 + (i % 25)];
        s += v; q += v*v;
    }
    __shared__ float rs[256], rq[256];
    rs[t] = s; rq[t] = q; __syncthreads();
    for (int o = 128; o > 0; o >>= 1){ if (t < o){ rs[t]+=rs[t+o]; rq[t]+=rq[t+o]; } __syncthreads(); }
    if (t == 0){ g_part2[(c*16+p)*2] = rs[0]; g_part2[(c*16+p)*2+1] = rq[0]; }
}
__global__ void k_fin2(){
    int c = threadIdx.x; if (c >= 16) return;
    float s = 0.f, q = 0.f;
    for (int p = 0; p < 16; p++){ s += g_part2[(c*16+p)*2]; q += g_part2[(c*16+p)*2+1]; }
    float N = (float)(BATCH*25);
    float m = s / N; float v = q / N - m*m;
    g_bn2m[c] = m; g_bn2i[c] = 1.0f / sqrtf(v + 1e-5f);
}

__global__ void k_mm2(){
    __shared__ unsigned smn, smx;
    if (threadIdx.x == 0){ smn = 0xFFFFFFFFu; smx = 0u; }
    __syncthreads();
    unsigned lmn = 0xFFFFFFFFu, lmx = 0u;
    int stride = gridDim.x * blockDim.x;
    for (int i = blockIdx.x*blockDim.x + threadIdx.x; i < N_P2; i += stride){
        int c = (i / 25) % 16;
        float v = g_p2[i];
        float y = fmaxf((v - g_bn2m[c]) * g_bn2i[c], 0.f);
        unsigned e = fenc(y);
        lmn = min(lmn, e); lmx = max(lmx, e);
    }
    atomicMin(&smn, lmn); atomicMax(&smx, lmx);
    __syncthreads();
    if (threadIdx.x == 0){ atomicMin(&g_mm[4], smn); atomicMax(&g_mm[5], smx); }
}

/* ---- fc1: (bn2+relu+quant on load) 400->128, relu, track min/max ---- */
__global__ void k_fc1(const int* __restrict__ qb){
    __shared__ float As[128][17];
    __shared__ float Bs[16][132];
    __shared__ unsigned smn, smx;
    int t = threadIdx.x;
    if (t == 0){ smn = 0xFFFFFFFFu; smx = 0u; }
    int rblk = blockIdx.x * 128;
    float mn = fdec(g_mm[4]), mx = fdec(g_mm[5]);
    float lv = (float)((1 << qb[0]) - 1);
    float qs = (mx - mn) / lv;
    float acc[8][8];
    #pragma unroll
    for (int i = 0; i < 8; i++)
        #pragma unroll
        for (int j = 0; j < 8; j++) acc[i][j] = 0.f;
    int r0 = (t / 16) * 8, c0 = (t % 16) * 8;
    for (int kt = 0; kt < 400; kt += 16){
        for (int i = t; i < 2048; i += 256){
            int row = i / 16, kk = i % 16, k = kt + kk;
            int c = k / 25, rem = k % 25;
            float v = g_p2[((rblk + row)*16 + c)*25 + rem];
            float y = fmaxf((v - g_bn2m[c]) * g_bn2i[c], 0.f);
            As[row][kk] = fminf(fmaxf(rintf(y/qs), 0.f), lv) * qs;
        }
        for (int i = t; i < 2048; i += 256){
            int kk = i / 128, nn = i % 128;
            Bs[kk][nn] = g_w3t[(kt + kk)*128 + nn];
        }
        __syncthreads();
        #pragma unroll
        for (int kk = 0; kk < 16; kk++){
            float a[8], bb[8];
            #pragma unroll
            for (int i = 0; i < 8; i++) a[i] = As[r0+i][kk];
            #pragma unroll
            for (int j = 0; j < 8; j++) bb[j] = Bs[kk][c0+j];
            #pragma unroll
            for (int i = 0; i < 8; i++)
                #pragma unroll
                for (int j = 0; j < 8; j++) acc[i][j] = fmaf(a[i], bb[j], acc[i][j]);
        }
        __syncthreads();
    }
    float inv = g_inv[2];
    unsigned lmn = 0xFFFFFFFFu, lmx = 0u;
    #pragma unroll
    for (int i = 0; i < 8; i++)
        #pragma unroll
        for (int j = 0; j < 8; j++){
            float y = fmaxf(acc[i][j] * inv, 0.f);
            g_y3[(rblk + r0 + i)*128 + c0 + j] = y;
            unsigned e = fenc(y);
            lmn = min(lmn, e); lmx = max(lmx, e);
        }
    atomicMin(&smn, lmn); atomicMax(&smx, lmx);
    __syncthreads();
    if (t == 0){ atomicMin(&g_mm[6], smn); atomicMax(&g_mm[7], smx); }
}

/* ---- fc2 (quant on load) + log_softmax ---- */
__global__ void k_fc2(const int* __restrict__ qb, float* __restrict__ out){
    __shared__ float ws[1280];
    int t = threadIdx.x;
    for (int i = t; i < 1280; i += 256) ws[i] = g_w4[i];
    __syncthreads();
    float mn = fdec(g_mm[6]), mx = fdec(g_mm[7]);
    float lv = (float)((1 << qb[0]) - 1);
    float qs = (mx - mn) / lv;
    float inv = g_inv[3];
    int warp = t / 32, lane = t % 32;
    int b = blockIdx.x * 8 + warp;
    float acc[10];
    #pragma unroll
    for (int o = 0; o < 10; o++) acc[o] = 0.f;
    for (int k = lane; k < 128; k += 32){
        float y = g_y3[b*128 + k];
        float q = fminf(fmaxf(rintf(y/qs), 0.f), lv) * qs;
        #pragma unroll
        for (int o = 0; o < 10; o++) acc[o] = fmaf(q, ws[o*128 + k], acc[o]);
    }
    #pragma unroll
    for (int off = 16; off > 0; off >>= 1)
        #pragma unroll
        for (int o = 0; o < 10; o++) acc[o] += __shfl_down_sync(0xFFFFFFFFu, acc[o], off);
    if (lane == 0){
        float l[10], m = -1e30f;
        #pragma unroll
        for (int o = 0; o < 10; o++){ l[o] = acc[o] * inv; m = fmaxf(m, l[o]); }
        float s = 0.f;
        #pragma unroll
        for (int o = 0; o < 10; o++) s += expf(l[o] - m);
        float ls = logf(s);
        #pragma unroll
        for (int o = 0; o < 10; o++) out[b*10 + o] = l[o] - m - ls;
    }
}

extern "C" void kernel_launch(void* const* d_in, const int* in_sizes, int n_in,
                              void* d_out, int out_size)
{
    const float* x   = (const float*)d_in[0];
    const float* sc1 = (const float*)d_in[1];
    const float* sg1 = (const float*)d_in[2];
    const float* h11 = (const float*)d_in[3];
    const float* h10 = (const float*)d_in[4];
    const float* sc2 = (const float*)d_in[5];
    const float* sg2 = (const float*)d_in[6];
    const float* h21 = (const float*)d_in[7];
    const float* h20 = (const float*)d_in[8];
    const float* sc3 = (const float*)d_in[9];
    const float* sg3 = (const float*)d_in[10];
    const float* h31 = (const float*)d_in[11];
    const float* h30 = (const float*)d_in[12];
    const float* sc4 = (const float*)d_in[13];
    const float* sg4 = (const float*)d_in[14];
    const float* h41 = (const float*)d_in[15];
    const float* h40 = (const float*)d_in[16];
    const int*   qb  = (const int*)d_in[17 <= n_in-1 ? 17 : n_in-1]; /* qb is last */
    float* out = (float*)d_out;

    cudaFuncSetAttribute(k_conv2, cudaFuncAttributeMaxDynamicSharedMemorySize, 76864);

    k_init<<<1, 32>>>();
    k_pool0<<<1568, 256>>>(x);
    k_quant0<<<1568, 256>>>(qb);

    k_wgen<<<1, 1024>>>(sc1, sg1, h11, h10, 0, 576,   2.0f/3.0f);
    k_wgen<<<1, 1024>>>(sc2, sg2, h21, h20, 1, 9216,  2.0f/24.0f);
    k_wgen<<<1, 1024>>>(sc3, sg3, h31, h30, 2, 51200, 2.0f/20.0f);
    k_wgen<<<1, 1024>>>(sc4, sg4, h41, h40, 3, 1280,  (float)(2.0/sqrt(128.0)));
    k_transp3<<<200, 256>>>();

    k_conv1<<<BATCH, 256>>>();
    k_stats1<<<dim3(64, 64), 256>>>();
    k_fin1<<<1, 64>>>();
    k_mm1<<<4096, 256>>>();

    k_conv2<<<BATCH, 160, 76864>>>(qb);
    k_pool2<<<1600, 256>>>();
    k_stats2<<<dim3(16, 16), 256>>>();
    k_fin2<<<1, 16>>>();
    k_mm2<<<1600, 256>>>();

    k_fc1<<<32, 256>>>(qb);
    k_fc2<<<512, 256>>>(qb, out);
}

// round 3
// speedup vs baseline: 1.2673x; 1.2673x over previous
#include <cuda_runtime.h>
#include <math.h>

typedef unsigned long long u64;

#define BATCH 4096
#define N_A0 (BATCH*196)
#define N_Z1 (BATCH*64*144)
#define N_P2 (BATCH*16*25)
#define N_Y3 (BATCH*128)

__device__ float g_a0raw[N_A0];
__device__ float g_z1[N_Z1];
__device__ float g_p2[N_P2];
__device__ float g_y3[N_Y3];
__device__ float g_w1[576];
__device__ float g_w2[9216];
__device__ float g_w3t[51200];
__device__ float g_w4[1280];
__device__ float g_inv[4];
__device__ float g_bn1m[64], g_bn1i[64];
__device__ float g_bn2m[16], g_bn2i[16];
__device__ float g_ps1[64*4096], g_pq1[64*4096];
__device__ float g_ps2[16*4096], g_pq2[16*4096];
__device__ unsigned g_cmn1[64], g_cmx1[64];
__device__ unsigned g_cmn2[16], g_cmx2[16];
__device__ unsigned g_mm[8];
__device__ float g_qmm[4];

__device__ __forceinline__ unsigned fenc(float f){
    unsigned u = __float_as_uint(f);
    return (u & 0x80000000u) ? ~u : (u | 0x80000000u);
}
__device__ __forceinline__ float fdec(unsigned u){
    return (u & 0x80000000u) ? __uint_as_float(u & 0x7FFFFFFFu) : __uint_as_float(~u);
}
__device__ __forceinline__ u64 pack2(float a, float b){
    u64 r; asm("mov.b64 %0, {%1, %2};" : "=l"(r) : "f"(a), "f"(b)); return r;
}
__device__ __forceinline__ void fma2(u64 &d, u64 a, u64 b){
    asm("fma.rn.f32x2 %0, %1, %2, %0;" : "+l"(d) : "l"(a), "l"(b));
}
__device__ __forceinline__ float2 unpack2(u64 v){
    float2 f; asm("mov.b64 {%0, %1}, %2;" : "=f"(f.x), "=f"(f.y) : "l"(v)); return f;
}

__global__ void k_init(){
    int t = threadIdx.x;
    if (t < 8)  g_mm[t] = (t & 1) ? 0u : 0xFFFFFFFFu;
    if (t < 64){ g_cmn1[t] = 0xFFFFFFFFu; g_cmx1[t] = 0u; }
    if (t < 16){ g_cmn2[t] = 0xFFFFFFFFu; g_cmx2[t] = 0u; }
}

/* ---- maxpool 28->14 + global min/max ---- */
__global__ void k_pool0(const float* __restrict__ x){
    __shared__ unsigned smn, smx;
    if (threadIdx.x == 0){ smn = 0xFFFFFFFFu; smx = 0u; }
    __syncthreads();
    unsigned lmn = 0xFFFFFFFFu, lmx = 0u;
    int stride = gridDim.x * blockDim.x;
    for (int o = blockIdx.x*blockDim.x + threadIdx.x; o < N_A0; o += stride){
        int b = o / 196, p = o % 196, r = p / 14, c = p % 14;
        const float* px = &x[b*784 + (r*2)*28 + c*2];
        float v = fmaxf(fmaxf(px[0], px[1]), fmaxf(px[28], px[29]));
        g_a0raw[o] = v;
        unsigned e = fenc(v);
        lmn = min(lmn, e); lmx = max(lmx, e);
    }
    atomicMin(&smn, lmn); atomicMax(&smx, lmx);
    __syncthreads();
    if (threadIdx.x == 0){ atomicMin(&g_mm[0], smn); atomicMax(&g_mm[1], smx); }
}

/* ---- weight gen for all 4 layers, one block each ---- */
__global__ void k_wgen4(const float* s1,const float* g1,const float* a1,const float* b1,
                        const float* s2,const float* g2,const float* a2,const float* b2,
                        const float* s3,const float* g3,const float* a3,const float* b3,
                        const float* s4,const float* g4,const float* a4,const float* b4)
{
    int L = blockIdx.x;
    const float *sc, *sg, *h1, *h0; int n; float coeff;
    if (L == 0){ sc=s1; sg=g1; h1=a1; h0=b1; n=576;   coeff=0.666666667f; }
    else if (L == 1){ sc=s2; sg=g2; h1=a2; h0=b2; n=9216;  coeff=0.0833333333f; }
    else if (L == 2){ sc=s3; sg=g3; h1=a3; h0=b3; n=51200; coeff=0.1f; }
    else            { sc=s4; sg=g4; h1=a4; h0=b4; n=1280;  coeff=0.17677669529663689f; }

    __shared__ float red[1024];
    __shared__ unsigned hist[256];
    __shared__ unsigned sh_pref;
    __shared__ int sh_rank;
    __shared__ int ties[2048];
    __shared__ int ntie, Gtot, Cidx;
    int t = threadIdx.x;

    float s = 0.f;
    for (int i = t; i < n; i += 1024) s += h1[i];
    red[t] = s; __syncthreads();
    for (int o = 512; o > 0; o >>= 1){ if (t < o) red[t] += red[t+o]; __syncthreads(); }
    if (t == 0) g_inv[L] = coeff / (red[0] / (float)n);

    unsigned pref = 0; int rank = n >> 1;
    for (int shift = 24; shift >= 0; shift -= 8){
        if (t < 256) hist[t] = 0;
        __syncthreads();
        unsigned mask = (shift < 24) ? (0xFFFFFFFFu << (shift+8)) : 0u;
        for (int i = t; i < n; i += 1024){
            unsigned k = __float_as_uint(fabsf(sc[i]));
            if ((k & mask) == (pref & mask)) atomicAdd(&hist[(k >> shift) & 255], 1u);
        }
        __syncthreads();
        if (t == 0){
            unsigned c = 0; int d = 0;
            for (; d < 255; d++){ if (c + hist[d] > (unsigned)rank) break; c += hist[d]; }
            sh_pref = pref | ((unsigned)d << shift);
            sh_rank = rank - (int)c;
        }
        __syncthreads();
        pref = sh_pref; rank = sh_rank;
        __syncthreads();
    }
    unsigned thr = pref;
    if (t == 0){ ntie = 0; Gtot = 0; }
    __syncthreads();
    int g = 0;
    for (int i = t; i < n; i += 1024){
        unsigned k = __float_as_uint(fabsf(sc[i]));
        if (k > thr) g++;
        else if (k == thr){ int p = atomicAdd(&ntie, 1); if (p < 2048) ties[p] = i; }
    }
    atomicAdd(&Gtot, g);
    __syncthreads();
    if (t == 0){
        int E = ntie; if (E > 2048) E = 2048;
        for (int a = 1; a < E; a++){
            int v = ties[a]; int b2 = a - 1;
            while (b2 >= 0 && ties[b2] > v){ ties[b2+1] = ties[b2]; b2--; }
            ties[b2+1] = v;
        }
        int T1 = (n - (n >> 1)) - Gtot;
        if (T1 < 1) T1 = 1; if (T1 > E) T1 = E;
        Cidx = ties[E - T1];
    }
    __syncthreads();
    int C = Cidx;
    for (int i = t; i < n; i += 1024){
        unsigned k = __float_as_uint(fabsf(sc[i]));
        bool m = (k > thr) || (k == thr && i >= C);
        float val = sg[i] * (m ? h1[i] : h0[i]);
        if (L == 2) g_w3t[(i % 400)*128 + (i / 400)] = val;
        else if (L == 0) g_w1[i] = val;
        else if (L == 1) g_w2[i] = val;
        else g_w4[i] = val;
    }
}

/* ---- conv1 + quant-on-load + fused per-channel stats/minmax ---- */
__global__ void k_conv1(const int* __restrict__ qb){
    __shared__ float in_s[196];
    __shared__ float ws[576];
    __shared__ float z_s[64*145];
    int b = blockIdx.x, t = threadIdx.x;   /* 160 threads */
    float mn = fdec(g_mm[0]), mx = fdec(g_mm[1]);
    float lv = (float)((1 << qb[0]) - 1);
    float sc = (mx - mn) / lv;
    float zp = floorf(mn / sc);
    float rsc = 1.0f / sc;
    for (int i = t; i < 196; i += 160){
        float v = g_a0raw[b*196 + i];
        in_s[i] = (rintf((v - mn)*rsc) + zp)*sc;
    }
    for (int i = t; i < 576; i += 160) ws[i] = g_w1[i];
    __syncthreads();
    float inv = g_inv[0];
    if (t < 144){
        int pr = t / 12, pc = t % 12;
        float x0 = in_s[pr*14+pc],     x1 = in_s[pr*14+pc+1],     x2 = in_s[pr*14+pc+2];
        float x3 = in_s[(pr+1)*14+pc], x4 = in_s[(pr+1)*14+pc+1], x5 = in_s[(pr+1)*14+pc+2];
        float x6 = in_s[(pr+2)*14+pc], x7 = in_s[(pr+2)*14+pc+1], x8 = in_s[(pr+2)*14+pc+2];
        for (int co = 0; co < 64; co++){
            const float* w = &ws[co*9];
            float a = x0*w[0];
            a = fmaf(x1, w[1], a); a = fmaf(x2, w[2], a);
            a = fmaf(x3, w[3], a); a = fmaf(x4, w[4], a);
            a = fmaf(x5, w[5], a); a = fmaf(x6, w[6], a);
            a = fmaf(x7, w[7], a); a = fmaf(x8, w[8], a);
            float y = a * inv;
            z_s[co*145 + t] = y;
            g_z1[(b*64 + co)*144 + t] = y;
        }
    }
    __syncthreads();
    if (t < 64){
        float s = 0.f, q = 0.f;
        unsigned emn = 0xFFFFFFFFu, emx = 0u;
        for (int j = 0; j < 144; j++){
            float y = z_s[t*145 + j];
            s += y; q += y*y;
            unsigned e = fenc(y);
            emn = min(emn, e); emx = max(emx, e);
        }
        g_ps1[t*4096 + b] = s; g_pq1[t*4096 + b] = q;
        atomicMin(&g_cmn1[t], emn); atomicMax(&g_cmx1[t], emx);
    }
}

__global__ void k_fin1(){
    int c = blockIdx.x, t = threadIdx.x;
    float s = 0.f, q = 0.f;
    for (int i = t; i < 4096; i += 256){ s += g_ps1[c*4096+i]; q += g_pq1[c*4096+i]; }
    __shared__ float rs[256], rq[256];
    rs[t] = s; rq[t] = q; __syncthreads();
    for (int o = 128; o > 0; o >>= 1){ if (t < o){ rs[t]+=rs[t+o]; rq[t]+=rq[t+o]; } __syncthreads(); }
    if (t == 0){
        float N = (float)(BATCH*144);
        float m = rs[0] / N; float v = rq[0] / N - m*m;
        g_bn1m[c] = m; g_bn1i[c] = 1.0f / sqrtf(v + 1e-5f);
    }
}

__global__ void k_q1(){
    __shared__ float smn[64], smx[64];
    int t = threadIdx.x;
    float m = g_bn1m[t], iv = g_bn1i[t];
    smn[t] = fmaxf((fdec(g_cmn1[t]) - m)*iv, 0.f);
    smx[t] = fmaxf((fdec(g_cmx1[t]) - m)*iv, 0.f);
    __syncthreads();
    for (int o = 32; o > 0; o >>= 1){
        if (t < o){ smn[t] = fminf(smn[t], smn[t+o]); smx[t] = fmaxf(smx[t], smx[t+o]); }
        __syncthreads();
    }
    if (t == 0){ g_qmm[0] = smn[0]; g_qmm[1] = smx[0]; }
}

/* ---- conv2: bn1+relu+quant on load; f32x2 FMA; in-register maxpool;
        fused per-channel stats + minmax ---- */
__global__ void k_conv2(const int* __restrict__ qb){
    extern __shared__ float sm[];
    float* in2 = sm;                 /* 2*64*144 = 18432 floats  */
    float* ws  = sm + 18432;         /* 16*577  =  9232 floats  */
    int b2 = blockIdx.x, t = threadIdx.x;   /* 160 threads, 2 images */
    float lv = (float)((1 << qb[0]) - 1);
    float qs = (g_qmm[1] - g_qmm[0]) / lv;
    float rq = 1.0f / qs;
    const float* zsrc = &g_z1[b2*18432];
    for (int i = t; i < 18432; i += 160){
        int ci = (i % 9216) / 144;
        float v = zsrc[i];
        float y = fmaxf((v - g_bn1m[ci]) * g_bn1i[ci], 0.f);
        in2[i] = fminf(fmaxf(rintf(y*rq), 0.f), lv) * qs;
    }
    for (int i = t; i < 9216; i += 160)
        ws[(i/576)*577 + (i%576)] = g_w2[i];
    __syncthreads();

    int img = t / 80, r80 = t % 80;
    int co = r80 / 5, hp = r80 % 5;
    const float4* base4 = (const float4*)(in2 + img*9216);
    u64 acc[2][5];
    u64 zz = pack2(0.f, 0.f);
    #pragma unroll
    for (int o = 0; o < 2; o++)
        #pragma unroll
        for (int p = 0; p < 5; p++) acc[o][p] = zz;

    #pragma unroll 1
    for (int ci = 0; ci < 64; ci++){
        const float* wr = &ws[co*577 + ci*9];
        u64 wp[3][3];
        #pragma unroll
        for (int kh = 0; kh < 3; kh++)
            #pragma unroll
            for (int kw = 0; kw < 3; kw++){ float w = wr[kh*3+kw]; wp[kh][kw] = pack2(w, w); }
        #pragma unroll
        for (int lr = 0; lr < 4; lr++){
            int row = hp*2 + lr;
            float4 v0 = base4[ci*36 + row*3 + 0];
            float4 v1 = base4[ci*36 + row*3 + 1];
            float4 v2 = base4[ci*36 + row*3 + 2];
            u64 E[6], O[5];
            E[0] = pack2(v0.x, v0.y); E[1] = pack2(v0.z, v0.w);
            E[2] = pack2(v1.x, v1.y); E[3] = pack2(v1.z, v1.w);
            E[4] = pack2(v2.x, v2.y); E[5] = pack2(v2.z, v2.w);
            O[0] = pack2(v0.y, v0.z); O[1] = pack2(v0.w, v1.x);
            O[2] = pack2(v1.y, v1.z); O[3] = pack2(v1.w, v2.x);
            O[4] = pack2(v2.y, v2.z);
            if (lr <= 2){
                int kh = lr;
                #pragma unroll
                for (int p = 0; p < 5; p++) fma2(acc[0][p], E[p],   wp[kh][0]);
                #pragma unroll
                for (int p = 0; p < 5; p++) fma2(acc[0][p], O[p],   wp[kh][1]);
                #pragma unroll
                for (int p = 0; p < 5; p++) fma2(acc[0][p], E[p+1], wp[kh][2]);
            }
            if (lr >= 1){
                int kh = lr - 1;
                #pragma unroll
                for (int p = 0; p < 5; p++) fma2(acc[1][p], E[p],   wp[kh][0]);
                #pragma unroll
                for (int p = 0; p < 5; p++) fma2(acc[1][p], O[p],   wp[kh][1]);
                #pragma unroll
                for (int p = 0; p < 5; p++) fma2(acc[1][p], E[p+1], wp[kh][2]);
            }
        }
    }

    float inv = g_inv[1];
    float s5 = 0.f, q5 = 0.f;
    unsigned mn5 = 0xFFFFFFFFu, mx5 = 0u;
    int bb = b2*2 + img;
    float* dst = &g_p2[(bb*16 + co)*25 + hp*5];
    #pragma unroll
    for (int p = 0; p < 5; p++){
        float2 a0 = unpack2(acc[0][p]), a1 = unpack2(acc[1][p]);
        float v = fmaxf(fmaxf(a0.x, a0.y), fmaxf(a1.x, a1.y)) * inv;
        dst[p] = v;
        s5 += v; q5 += v*v;
        unsigned e = fenc(v);
        mn5 = min(mn5, e); mx5 = max(mx5, e);
    }
    __syncthreads();
    sm[t] = s5; sm[160 + t] = q5;
    ((unsigned*)sm)[320 + t] = mn5; ((unsigned*)sm)[480 + t] = mx5;
    __syncthreads();
    if (t < 32){
        int im = t >> 4, c = t & 15;
        int base = im*80 + c*5;
        float s = 0.f, q = 0.f;
        unsigned mn = 0xFFFFFFFFu, mx = 0u;
        for (int h = 0; h < 5; h++){
            s += sm[base + h]; q += sm[160 + base + h];
            mn = min(mn, ((unsigned*)sm)[320 + base + h]);
            mx = max(mx, ((unsigned*)sm)[480 + base + h]);
        }
        int bimg = b2*2 + im;
        g_ps2[c*4096 + bimg] = s; g_pq2[c*4096 + bimg] = q;
        atomicMin(&g_cmn2[c], mn); atomicMax(&g_cmx2[c], mx);
    }
}

__global__ void k_fin2(){
    int c = blockIdx.x, t = threadIdx.x;
    float s = 0.f, q = 0.f;
    for (int i = t; i < 4096; i += 256){ s += g_ps2[c*4096+i]; q += g_pq2[c*4096+i]; }
    __shared__ float rs[256], rq[256];
    rs[t] = s; rq[t] = q; __syncthreads();
    for (int o = 128; o > 0; o >>= 1){ if (t < o){ rs[t]+=rs[t+o]; rq[t]+=rq[t+o]; } __syncthreads(); }
    if (t == 0){
        float N = (float)(BATCH*25);
        float m = rs[0] / N; float v = rq[0] / N - m*m;
        g_bn2m[c] = m; g_bn2i[c] = 1.0f / sqrtf(v + 1e-5f);
    }
}

__global__ void k_q2(){
    __shared__ float smn[16], smx[16];
    int t = threadIdx.x;
    float m = g_bn2m[t], iv = g_bn2i[t];
    smn[t] = fmaxf((fdec(g_cmn2[t]) - m)*iv, 0.f);
    smx[t] = fmaxf((fdec(g_cmx2[t]) - m)*iv, 0.f);
    __syncthreads();
    for (int o = 8; o > 0; o >>= 1){
        if (t < o){ smn[t] = fminf(smn[t], smn[t+o]); smx[t] = fmaxf(smx[t], smx[t+o]); }
        __syncthreads();
    }
    if (t == 0){ g_qmm[2] = smn[0]; g_qmm[3] = smx[0]; }
}

/* ---- fc1: (bn2+relu+quant on load) 400->128, relu, minmax ---- */
__global__ void k_fc1(const int* __restrict__ qb){
    __shared__ float As[32][17];
    __shared__ float Bs[16][132];
    __shared__ unsigned smn, smx;
    int t = threadIdx.x;
    if (t == 0){ smn = 0xFFFFFFFFu; smx = 0u; }
    int rblk = blockIdx.x * 32;
    float lv = (float)((1 << qb[0]) - 1);
    float qs = (g_qmm[3] - g_qmm[2]) / lv;
    float rq = 1.0f / qs;
    float acc[4][4];
    #pragma unroll
    for (int i = 0; i < 4; i++)
        #pragma unroll
        for (int j = 0; j < 4; j++) acc[i][j] = 0.f;
    int rg = (t >> 5) * 4, c0 = t & 31;
    for (int kt = 0; kt < 400; kt += 16){
        for (int i = t; i < 512; i += 256){
            int row = i >> 4, kk = i & 15, k = kt + kk;
            int c = k / 25, rem = k % 25;
            float v = g_p2[((rblk + row)*16 + c)*25 + rem];
            float y = fmaxf((v - g_bn2m[c]) * g_bn2i[c], 0.f);
            As[row][kk] = fminf(fmaxf(rintf(y*rq), 0.f), lv) * qs;
        }
        for (int i = t; i < 2048; i += 256){
            int kk = i >> 7, nn = i & 127;
            Bs[kk][nn] = g_w3t[(kt + kk)*128 + nn];
        }
        __syncthreads();
        #pragma unroll
        for (int kk = 0; kk < 16; kk++){
            float a0 = As[rg][kk], a1 = As[rg+1][kk], a2 = As[rg+2][kk], a3 = As[rg+3][kk];
            float b0 = Bs[kk][c0], b1 = Bs[kk][c0+32], b2 = Bs[kk][c0+64], b3 = Bs[kk][c0+96];
            acc[0][0]=fmaf(a0,b0,acc[0][0]); acc[0][1]=fmaf(a0,b1,acc[0][1]);
            acc[0][2]=fmaf(a0,b2,acc[0][2]); acc[0][3]=fmaf(a0,b3,acc[0][3]);
            acc[1][0]=fmaf(a1,b0,acc[1][0]); acc[1][1]=fmaf(a1,b1,acc[1][1]);
            acc[1][2]=fmaf(a1,b2,acc[1][2]); acc[1][3]=fmaf(a1,b3,acc[1][3]);
            acc[2][0]=fmaf(a2,b0,acc[2][0]); acc[2][1]=fmaf(a2,b1,acc[2][1]);
            acc[2][2]=fmaf(a2,b2,acc[2][2]); acc[2][3]=fmaf(a2,b3,acc[2][3]);
            acc[3][0]=fmaf(a3,b0,acc[3][0]); acc[3][1]=fmaf(a3,b1,acc[3][1]);
            acc[3][2]=fmaf(a3,b2,acc[3][2]); acc[3][3]=fmaf(a3,b3,acc[3][3]);
        }
        __syncthreads();
    }
    float inv = g_inv[2];
    unsigned lmn = 0xFFFFFFFFu, lmx = 0u;
    #pragma unroll
    for (int ii = 0; ii < 4; ii++)
        #pragma unroll
        for (int jj = 0; jj < 4; jj++){
            float y = fmaxf(acc[ii][jj] * inv, 0.f);
            g_y3[(rblk + rg + ii)*128 + c0 + 32*jj] = y;
            unsigned e = fenc(y);
            lmn = min(lmn, e); lmx = max(lmx, e);
        }
    atomicMin(&smn, lmn); atomicMax(&smx, lmx);
    __syncthreads();
    if (t == 0){ atomicMin(&g_mm[6], smn); atomicMax(&g_mm[7], smx); }
}

/* ---- fc2 (quant on load) + log_softmax ---- */
__global__ void k_fc2(const int* __restrict__ qb, float* __restrict__ out){
    __shared__ float ws[1280];
    int t = threadIdx.x;
    for (int i = t; i < 1280; i += 256) ws[i] = g_w4[i];
    __syncthreads();
    float mn = fdec(g_mm[6]), mx = fdec(g_mm[7]);
    float lv = (float)((1 << qb[0]) - 1);
    float qs = (mx - mn) / lv;
    float rq = 1.0f / qs;
    float inv = g_inv[3];
    int warp = t / 32, lane = t % 32;
    int b = blockIdx.x * 8 + warp;
    float acc[10];
    #pragma unroll
    for (int o = 0; o < 10; o++) acc[o] = 0.f;
    for (int k = lane; k < 128; k += 32){
        float y = g_y3[b*128 + k];
        float q = fminf(fmaxf(rintf(y*rq), 0.f), lv) * qs;
        #pragma unroll
        for (int o = 0; o < 10; o++) acc[o] = fmaf(q, ws[o*128 + k], acc[o]);
    }
    #pragma unroll
    for (int off = 16; off > 0; off >>= 1)
        #pragma unroll
        for (int o = 0; o < 10; o++) acc[o] += __shfl_down_sync(0xFFFFFFFFu, acc[o], off);
    if (lane == 0){
        float l[10], m = -1e30f;
        #pragma unroll
        for (int o = 0; o < 10; o++){ l[o] = acc[o] * inv; m = fmaxf(m, l[o]); }
        float s = 0.f;
        #pragma unroll
        for (int o = 0; o < 10; o++) s += expf(l[o] - m);
        float ls = logf(s);
        #pragma unroll
        for (int o = 0; o < 10; o++) out[b*10 + o] = l[o] - m - ls;
    }
}

extern "C" void kernel_launch(void* const* d_in, const int* in_sizes, int n_in,
                              void* d_out, int out_size)
{
    const float* x   = (const float*)d_in[0];
    const float* sc1 = (const float*)d_in[1];
    const float* sg1 = (const float*)d_in[2];
    const float* h11 = (const float*)d_in[3];
    const float* h10 = (const float*)d_in[4];
    const float* sc2 = (const float*)d_in[5];
    const float* sg2 = (const float*)d_in[6];
    const float* h21 = (const float*)d_in[7];
    const float* h20 = (const float*)d_in[8];
    const float* sc3 = (const float*)d_in[9];
    const float* sg3 = (const float*)d_in[10];
    const float* h31 = (const float*)d_in[11];
    const float* h30 = (const float*)d_in[12];
    const float* sc4 = (const float*)d_in[13];
    const float* sg4 = (const float*)d_in[14];
    const float* h41 = (const float*)d_in[15];
    const float* h40 = (const float*)d_in[16];
    const int*   qb  = (const int*)d_in[17];
    float* out = (float*)d_out;

    cudaFuncSetAttribute(k_conv2, cudaFuncAttributeMaxDynamicSharedMemorySize, 110656);

    k_init<<<1, 128>>>();
    k_pool0<<<1568, 256>>>(x);
    k_wgen4<<<4, 1024>>>(sc1, sg1, h11, h10,
                         sc2, sg2, h21, h20,
                         sc3, sg3, h31, h30,
                         sc4, sg4, h41, h40);
    k_conv1<<<BATCH, 160>>>(qb);
    k_fin1<<<64, 256>>>();
    k_q1<<<1, 64>>>();
    k_conv2<<<2048, 160, 110656>>>(qb);
    k_fin2<<<16, 256>>>();
    k_q2<<<1, 16>>>();
    k_fc1<<<128, 256>>>(qb);
    k_fc2<<<512, 256>>>(qb, out);
}

// round 4
// speedup vs baseline: 2.5173x; 1.9863x over previous
#include <cuda_runtime.h>
#include <math.h>

typedef unsigned long long u64;

#define BATCH 4096

__device__ float g_a0raw[BATCH*196];
__device__ float g_p2[BATCH*16*25];
__device__ float g_y3[BATCH*128];
__device__ float g_w1[576];
__device__ float g_w2[9216];
__device__ float g_w3t[51200];
__device__ float g_w4[1280];
__device__ float g_inv[4];
__device__ float g_bn1m[64], g_bn1i[64];
__device__ float g_bn2m[16], g_bn2i[16];
__device__ float g_ps1[64*4096], g_pq1[64*4096];
__device__ float g_ps2[16*4096], g_pq2[16*4096];
__device__ unsigned g_cmn1[64], g_cmx1[64];
__device__ unsigned g_cmn2[16], g_cmx2[16];
__device__ unsigned g_mm[8];
__device__ float g_qmm[4];

__device__ __forceinline__ unsigned fenc(float f){
    unsigned u = __float_as_uint(f);
    return (u & 0x80000000u) ? ~u : (u | 0x80000000u);
}
__device__ __forceinline__ float fdec(unsigned u){
    return (u & 0x80000000u) ? __uint_as_float(u & 0x7FFFFFFFu) : __uint_as_float(~u);
}
__device__ __forceinline__ u64 pack2(float a, float b){
    u64 r; asm("mov.b64 %0, {%1, %2};" : "=l"(r) : "f"(a), "f"(b)); return r;
}
__device__ __forceinline__ void fma2(u64 &d, u64 a, u64 b){
    asm("fma.rn.f32x2 %0, %1, %2, %0;" : "+l"(d) : "l"(a), "l"(b));
}
__device__ __forceinline__ float2 unpack2(u64 v){
    float2 f; asm("mov.b64 {%0, %1}, %2;" : "=f"(f.x), "=f"(f.y) : "l"(v)); return f;
}

/* identical quantization expression in conv1s and conv2 (bit-exact pairing) */
#define QUANTA0(v) (__fmul_rn(__fadd_rn(rintf(__fmul_rn(__fsub_rn((v),mn),rsc)), zp), sc))

/* one kh-row of the 12-wide conv1: 6 output pairs, kw order 0,1,2 */
#define C1ROW(Earr, wa, wb, wc) do{ \
    _Pragma("unroll") \
    for (int j = 0; j < 6; j++){ \
        float2 _lo = unpack2(Earr[j]); float2 _hi = unpack2(Earr[j+1]); \
        u64 _O = pack2(_lo.y, _hi.x); \
        fma2(acc[j], Earr[j],   wa); \
        fma2(acc[j], _O,        wb); \
        fma2(acc[j], Earr[j+1], wc); \
    } }while(0)

#define LOADROW(Ap, r, E) do{ \
    const float2* _p = (const float2*)((Ap) + (r)*14); \
    _Pragma("unroll") \
    for (int j = 0; j < 7; j++){ float2 _v = _p[j]; E[j] = pack2(_v.x, _v.y); } }while(0)

__global__ void k_init(){
    int t = threadIdx.x;
    if (t < 8)  g_mm[t] = (t & 1) ? 0u : 0xFFFFFFFFu;
    if (t < 64){ g_cmn1[t] = 0xFFFFFFFFu; g_cmx1[t] = 0u; }
    if (t < 16){ g_cmn2[t] = 0xFFFFFFFFu; g_cmx2[t] = 0u; }
}

/* ---- maxpool 28->14 (float4 vectorized) + global min/max ---- */
__global__ void k_pool0(const float* __restrict__ x){
    __shared__ unsigned smn, smx;
    if (threadIdx.x == 0){ smn = 0xFFFFFFFFu; smx = 0u; }
    __syncthreads();
    int idx = blockIdx.x*blockDim.x + threadIdx.x;   /* 401408 total */
    int b = idx / 98, rem = idx % 98, r = rem / 7, cq = rem % 7;
    const float4* p0 = (const float4*)&x[b*784 + (r*2)*28 + cq*4];
    const float4* p1 = (const float4*)&x[b*784 + (r*2+1)*28 + cq*4];
    float4 a = *p0, c = *p1;
    float o0 = fmaxf(fmaxf(a.x, a.y), fmaxf(c.x, c.y));
    float o1 = fmaxf(fmaxf(a.z, a.w), fmaxf(c.z, c.w));
    float2 o; o.x = o0; o.y = o1;
    *(float2*)&g_a0raw[b*196 + r*14 + cq*2] = o;
    unsigned e0 = fenc(o0), e1 = fenc(o1);
    unsigned lmn = min(e0, e1), lmx = max(e0, e1);
    atomicMin(&smn, lmn); atomicMax(&smx, lmx);
    __syncthreads();
    if (threadIdx.x == 0){ atomicMin(&g_mm[0], smn); atomicMax(&g_mm[1], smx); }
}

/* ---- weight gen for all 4 layers, one block each ---- */
__global__ void k_wgen4(const float* s1,const float* g1,const float* a1,const float* b1,
                        const float* s2,const float* g2,const float* a2,const float* b2,
                        const float* s3,const float* g3,const float* a3,const float* b3,
                        const float* s4,const float* g4,const float* a4,const float* b4)
{
    int L = blockIdx.x;
    const float *sc, *sg, *h1, *h0; int n; float coeff;
    if (L == 0){ sc=s1; sg=g1; h1=a1; h0=b1; n=576;   coeff=0.666666667f; }
    else if (L == 1){ sc=s2; sg=g2; h1=a2; h0=b2; n=9216;  coeff=0.0833333333f; }
    else if (L == 2){ sc=s3; sg=g3; h1=a3; h0=b3; n=51200; coeff=0.1f; }
    else            { sc=s4; sg=g4; h1=a4; h0=b4; n=1280;  coeff=0.17677669529663689f; }

    __shared__ float red[1024];
    __shared__ unsigned hist[4][256];
    __shared__ unsigned sh_pref;
    __shared__ int sh_rank;
    __shared__ int ties[2048];
    __shared__ int ntie, Gtot, Cidx;
    int t = threadIdx.x;
    int hg = t >> 8;                  /* 4 sub-histograms */

    float s = 0.f;
    for (int i = t; i < n; i += 1024) s += h1[i];
    red[t] = s; __syncthreads();
    for (int o = 512; o > 0; o >>= 1){ if (t < o) red[t] += red[t+o]; __syncthreads(); }
    if (t == 0) g_inv[L] = coeff / (red[0] / (float)n);

    unsigned pref = 0; int rank = n >> 1;
    for (int shift = 24; shift >= 0; shift -= 8){
        if (t < 256){ hist[0][t]=0; hist[1][t]=0; hist[2][t]=0; hist[3][t]=0; }
        __syncthreads();
        unsigned mask = (shift < 24) ? (0xFFFFFFFFu << (shift+8)) : 0u;
        for (int i = t; i < n; i += 1024){
            unsigned k = __float_as_uint(fabsf(sc[i]));
            if ((k & mask) == (pref & mask)) atomicAdd(&hist[hg][(k >> shift) & 255], 1u);
        }
        __syncthreads();
        if (t == 0){
            unsigned c = 0; int d = 0;
            for (; d < 255; d++){
                unsigned hd = hist[0][d]+hist[1][d]+hist[2][d]+hist[3][d];
                if (c + hd > (unsigned)rank) break; c += hd;
            }
            sh_pref = pref | ((unsigned)d << shift);
            sh_rank = rank - (int)c;
        }
        __syncthreads();
        pref = sh_pref; rank = sh_rank;
        __syncthreads();
    }
    unsigned thr = pref;
    if (t == 0){ ntie = 0; Gtot = 0; }
    __syncthreads();
    int g = 0;
    for (int i = t; i < n; i += 1024){
        unsigned k = __float_as_uint(fabsf(sc[i]));
        if (k > thr) g++;
        else if (k == thr){ int p = atomicAdd(&ntie, 1); if (p < 2048) ties[p] = i; }
    }
    atomicAdd(&Gtot, g);
    __syncthreads();
    if (t == 0){
        int E = ntie; if (E > 2048) E = 2048;
        for (int a = 1; a < E; a++){
            int v = ties[a]; int b2 = a - 1;
            while (b2 >= 0 && ties[b2] > v){ ties[b2+1] = ties[b2]; b2--; }
            ties[b2+1] = v;
        }
        int T1 = (n - (n >> 1)) - Gtot;
        if (T1 < 1) T1 = 1; if (T1 > E) T1 = E;
        Cidx = ties[E - T1];
    }
    __syncthreads();
    int C = Cidx;
    for (int i = t; i < n; i += 1024){
        unsigned k = __float_as_uint(fabsf(sc[i]));
        bool m = (k > thr) || (k == thr && i >= C);
        float val = sg[i] * (m ? h1[i] : h0[i]);
        if (L == 2) g_w3t[(i % 400)*128 + (i / 400)] = val;
        else if (L == 0) g_w1[i] = val;
        else if (L == 1) g_w2[i] = val;
        else g_w4[i] = val;
    }
}

/* ---- conv1 stats only: no z1 tensor. thread=(img,channel), 4 img/block ---- */
__global__ void k_conv1s(const int* __restrict__ qb){
    __shared__ float a0s[4*196];
    int blk = blockIdx.x, t = threadIdx.x;   /* 256 */
    float mn = fdec(g_mm[0]), mx = fdec(g_mm[1]);
    float lv = (float)((1 << qb[0]) - 1);
    float sc = (mx - mn) / lv;
    float zp = floorf(mn / sc);
    float rsc = 1.0f / sc;
    for (int i = t; i < 784; i += 256)
        a0s[i] = QUANTA0(g_a0raw[blk*784 + i]);
    __syncthreads();
    int img = t >> 6, co = t & 63;
    u64 wp[9];
    #pragma unroll
    for (int k = 0; k < 9; k++){ float w = g_w1[co*9 + k]; wp[k] = pack2(w, w); }
    float inv = g_inv[0];
    const float* A = &a0s[img*196];
    float s = 0.f, q = 0.f;
    unsigned emn = 0xFFFFFFFFu, emx = 0u;

#define STATS1 do{ _Pragma("unroll") for (int j = 0; j < 6; j++){ \
        float2 f = unpack2(acc[j]); \
        float y0 = __fmul_rn(f.x, inv), y1 = __fmul_rn(f.y, inv); \
        s += y0; s += y1; q = fmaf(y0, y0, q); q = fmaf(y1, y1, q); \
        unsigned e0 = fenc(y0), e1 = fenc(y1); \
        emn = min(emn, min(e0, e1)); emx = max(emx, max(e0, e1)); }}while(0)

    u64 R0[7], R1[7], R2[7];
    LOADROW(A, 0, R0); LOADROW(A, 1, R1);
    #pragma unroll
    for (int pr3 = 0; pr3 < 12; pr3 += 3){
        { LOADROW(A, pr3+2, R2); u64 acc[6];
          #pragma unroll
          for (int j=0;j<6;j++) acc[j]=pack2(0.f,0.f);
          C1ROW(R0, wp[0],wp[1],wp[2]); C1ROW(R1, wp[3],wp[4],wp[5]); C1ROW(R2, wp[6],wp[7],wp[8]);
          STATS1; }
        { LOADROW(A, pr3+3, R0); u64 acc[6];
          #pragma unroll
          for (int j=0;j<6;j++) acc[j]=pack2(0.f,0.f);
          C1ROW(R1, wp[0],wp[1],wp[2]); C1ROW(R2, wp[3],wp[4],wp[5]); C1ROW(R0, wp[6],wp[7],wp[8]);
          STATS1; }
        { LOADROW(A, pr3+4, R1); u64 acc[6];
          #pragma unroll
          for (int j=0;j<6;j++) acc[j]=pack2(0.f,0.f);
          C1ROW(R2, wp[0],wp[1],wp[2]); C1ROW(R0, wp[3],wp[4],wp[5]); C1ROW(R1, wp[6],wp[7],wp[8]);
          STATS1; }
    }
#undef STATS1
    g_ps1[co*4096 + blk*4 + img] = s;
    g_pq1[co*4096 + blk*4 + img] = q;
    atomicMin(&g_cmn1[co], emn); atomicMax(&g_cmx1[co], emx);
}

__global__ void k_fin1(){
    int c = blockIdx.x, t = threadIdx.x;
    float s = 0.f, q = 0.f;
    for (int i = t; i < 4096; i += 256){ s += g_ps1[c*4096+i]; q += g_pq1[c*4096+i]; }
    __shared__ float rs[256], rq[256];
    rs[t] = s; rq[t] = q; __syncthreads();
    for (int o = 128; o > 0; o >>= 1){ if (t < o){ rs[t]+=rs[t+o]; rq[t]+=rq[t+o]; } __syncthreads(); }
    if (t == 0){
        float N = (float)(BATCH*144);
        float m = rs[0] / N; float v = rq[0] / N - m*m;
        g_bn1m[c] = m; g_bn1i[c] = 1.0f / sqrtf(v + 1e-5f);
    }
}

__global__ void k_q1(){
    __shared__ float smn[64], smx[64];
    int t = threadIdx.x;
    float m = g_bn1m[t], iv = g_bn1i[t];
    smn[t] = fmaxf(__fmul_rn(__fsub_rn(fdec(g_cmn1[t]), m), iv), 0.f);
    smx[t] = fmaxf(__fmul_rn(__fsub_rn(fdec(g_cmx1[t]), m), iv), 0.f);
    __syncthreads();
    for (int o = 32; o > 0; o >>= 1){
        if (t < o){ smn[t] = fminf(smn[t], smn[t+o]); smx[t] = fmaxf(smx[t], smx[t+o]); }
        __syncthreads();
    }
    if (t == 0){ g_qmm[0] = smn[0]; g_qmm[1] = smx[0]; }
}

/* ---- conv2 fused: recompute conv1 -> bn/relu/quant in smem -> conv2 (f32x2)
        -> in-register 2x2 maxpool -> fused per-channel stats ---- */
__global__ void __launch_bounds__(320, 1) k_conv2(const int* __restrict__ qb){
    extern __shared__ float sm[];
    float* in2 = sm;                 /* 4*9216 = 36864 */
    float* ws  = sm + 36864;         /* 16*577 =  9232 */
    float* a0s = sm + 46096;         /* 4*196  =   784 */
    float* w1s = sm + 46880;         /* 576           -> 47456 floats */
    int blk = blockIdx.x, t = threadIdx.x;   /* 320, 4 images */
    float mn = fdec(g_mm[0]), mx = fdec(g_mm[1]);
    float lv = (float)((1 << qb[0]) - 1);
    float sc = (mx - mn) / lv;
    float zp = floorf(mn / sc);
    float rsc = 1.0f / sc;
    for (int i = t; i < 784; i += 320)
        a0s[i] = QUANTA0(g_a0raw[blk*784 + i]);
    for (int i = t; i < 576; i += 320) w1s[i] = g_w1[i];
    for (int i = t; i < 9216; i += 320)
        ws[(i/576)*577 + (i%576)] = g_w2[i];
    __syncthreads();

    /* phase B: recompute quantized conv1 output into in2 (bit-exact vs k_conv1s) */
    float qs1 = (g_qmm[1] - g_qmm[0]) / lv;
    float rq1 = 1.0f / qs1;
    if (t < 256){
        int img = t >> 6, co = t & 63;
        u64 wp[9];
        #pragma unroll
        for (int k = 0; k < 9; k++){ float w = w1s[co*9 + k]; wp[k] = pack2(w, w); }
        float inv = g_inv[0];
        float m1 = g_bn1m[co], i1 = g_bn1i[co];
        const float* A = &a0s[img*196];
        float2* dst = (float2*)(in2 + img*9216 + co*144);

#define EMITB(PR) do{ _Pragma("unroll") for (int j = 0; j < 6; j++){ \
        float2 f = unpack2(acc[j]); \
        float y0 = __fmul_rn(f.x, inv), y1 = __fmul_rn(f.y, inv); \
        float u0 = fmaxf(__fmul_rn(__fsub_rn(y0, m1), i1), 0.f); \
        float u1 = fmaxf(__fmul_rn(__fsub_rn(y1, m1), i1), 0.f); \
        float2 o; \
        o.x = __fmul_rn(fminf(fmaxf(rintf(__fmul_rn(u0, rq1)), 0.f), lv), qs1); \
        o.y = __fmul_rn(fminf(fmaxf(rintf(__fmul_rn(u1, rq1)), 0.f), lv), qs1); \
        dst[(PR)*6 + j] = o; }}while(0)

        u64 R0[7], R1[7], R2[7];
        LOADROW(A, 0, R0); LOADROW(A, 1, R1);
        #pragma unroll
        for (int pr3 = 0; pr3 < 12; pr3 += 3){
            { LOADROW(A, pr3+2, R2); u64 acc[6];
              #pragma unroll
              for (int j=0;j<6;j++) acc[j]=pack2(0.f,0.f);
              C1ROW(R0, wp[0],wp[1],wp[2]); C1ROW(R1, wp[3],wp[4],wp[5]); C1ROW(R2, wp[6],wp[7],wp[8]);
              EMITB(pr3); }
            { LOADROW(A, pr3+3, R0); u64 acc[6];
              #pragma unroll
              for (int j=0;j<6;j++) acc[j]=pack2(0.f,0.f);
              C1ROW(R1, wp[0],wp[1],wp[2]); C1ROW(R2, wp[3],wp[4],wp[5]); C1ROW(R0, wp[6],wp[7],wp[8]);
              EMITB(pr3+1); }
            { LOADROW(A, pr3+4, R1); u64 acc[6];
              #pragma unroll
              for (int j=0;j<6;j++) acc[j]=pack2(0.f,0.f);
              C1ROW(R2, wp[0],wp[1],wp[2]); C1ROW(R0, wp[3],wp[4],wp[5]); C1ROW(R1, wp[6],wp[7],wp[8]);
              EMITB(pr3+2); }
        }
#undef EMITB
    }
    __syncthreads();

    /* phase C: conv2 with packed f32x2 FMA */
    int img = t / 80, r80 = t % 80;
    int co = r80 / 5, hp = r80 % 5;
    const float4* base4 = (const float4*)(in2 + img*9216);
    u64 acc2[2][5];
    u64 zz = pack2(0.f, 0.f);
    #pragma unroll
    for (int o = 0; o < 2; o++)
        #pragma unroll
        for (int p = 0; p < 5; p++) acc2[o][p] = zz;

    #pragma unroll 1
    for (int ci = 0; ci < 64; ci++){
        const float* wr = &ws[co*577 + ci*9];
        u64 wp2[3][3];
        #pragma unroll
        for (int kh = 0; kh < 3; kh++)
            #pragma unroll
            for (int kw = 0; kw < 3; kw++){ float w = wr[kh*3+kw]; wp2[kh][kw] = pack2(w, w); }
        #pragma unroll
        for (int lr = 0; lr < 4; lr++){
            int row = hp*2 + lr;
            float4 v0 = base4[ci*36 + row*3 + 0];
            float4 v1 = base4[ci*36 + row*3 + 1];
            float4 v2 = base4[ci*36 + row*3 + 2];
            u64 E[6], O[5];
            E[0] = pack2(v0.x, v0.y); E[1] = pack2(v0.z, v0.w);
            E[2] = pack2(v1.x, v1.y); E[3] = pack2(v1.z, v1.w);
            E[4] = pack2(v2.x, v2.y); E[5] = pack2(v2.z, v2.w);
            O[0] = pack2(v0.y, v0.z); O[1] = pack2(v0.w, v1.x);
            O[2] = pack2(v1.y, v1.z); O[3] = pack2(v1.w, v2.x);
            O[4] = pack2(v2.y, v2.z);
            if (lr <= 2){
                int kh = lr;
                #pragma unroll
                for (int p = 0; p < 5; p++) fma2(acc2[0][p], E[p],   wp2[kh][0]);
                #pragma unroll
                for (int p = 0; p < 5; p++) fma2(acc2[0][p], O[p],   wp2[kh][1]);
                #pragma unroll
                for (int p = 0; p < 5; p++) fma2(acc2[0][p], E[p+1], wp2[kh][2]);
            }
            if (lr >= 1){
                int kh = lr - 1;
                #pragma unroll
                for (int p = 0; p < 5; p++) fma2(acc2[1][p], E[p],   wp2[kh][0]);
                #pragma unroll
                for (int p = 0; p < 5; p++) fma2(acc2[1][p], O[p],   wp2[kh][1]);
                #pragma unroll
                for (int p = 0; p < 5; p++) fma2(acc2[1][p], E[p+1], wp2[kh][2]);
            }
        }
    }

    float inv2 = g_inv[1];
    float s5 = 0.f, q5 = 0.f;
    unsigned mn5 = 0xFFFFFFFFu, mx5 = 0u;
    int bimg = blk*4 + img;
    float* dstp = &g_p2[(bimg*16 + co)*25 + hp*5];
    #pragma unroll
    for (int p = 0; p < 5; p++){
        float2 a0 = unpack2(acc2[0][p]), a1 = unpack2(acc2[1][p]);
        float v = fmaxf(fmaxf(a0.x, a0.y), fmaxf(a1.x, a1.y)) * inv2;
        dstp[p] = v;
        s5 += v; q5 = fmaf(v, v, q5);
        unsigned e = fenc(v);
        mn5 = min(mn5, e); mx5 = max(mx5, e);
    }
    __syncthreads();
    float* s_s = sm; float* s_q = sm + 320;
    unsigned* s_mn = (unsigned*)(sm + 640); unsigned* s_mx = (unsigned*)(sm + 960);
    s_s[t] = s5; s_q[t] = q5; s_mn[t] = mn5; s_mx[t] = mx5;
    __syncthreads();
    if (t < 64){
        int im = t >> 4, c = t & 15;
        int base = im*80 + c*5;
        float s = 0.f, q = 0.f;
        unsigned lmn = 0xFFFFFFFFu, lmx = 0u;
        #pragma unroll
        for (int h = 0; h < 5; h++){
            s += s_s[base + h]; q += s_q[base + h];
            lmn = min(lmn, s_mn[base + h]);
            lmx = max(lmx, s_mx[base + h]);
        }
        int bi = blk*4 + im;
        g_ps2[c*4096 + bi] = s; g_pq2[c*4096 + bi] = q;
        atomicMin(&g_cmn2[c], lmn); atomicMax(&g_cmx2[c], lmx);
    }
}

__global__ void k_fin2(){
    int c = blockIdx.x, t = threadIdx.x;
    float s = 0.f, q = 0.f;
    for (int i = t; i < 4096; i += 256){ s += g_ps2[c*4096+i]; q += g_pq2[c*4096+i]; }
    __shared__ float rs[256], rq[256];
    rs[t] = s; rq[t] = q; __syncthreads();
    for (int o = 128; o > 0; o >>= 1){ if (t < o){ rs[t]+=rs[t+o]; rq[t]+=rq[t+o]; } __syncthreads(); }
    if (t == 0){
        float N = (float)(BATCH*25);
        float m = rs[0] / N; float v = rq[0] / N - m*m;
        g_bn2m[c] = m; g_bn2i[c] = 1.0f / sqrtf(v + 1e-5f);
    }
}

__global__ void k_q2(){
    __shared__ float smn[16], smx[16];
    int t = threadIdx.x;
    float m = g_bn2m[t], iv = g_bn2i[t];
    smn[t] = fmaxf(__fmul_rn(__fsub_rn(fdec(g_cmn2[t]), m), iv), 0.f);
    smx[t] = fmaxf(__fmul_rn(__fsub_rn(fdec(g_cmx2[t]), m), iv), 0.f);
    __syncthreads();
    for (int o = 8; o > 0; o >>= 1){
        if (t < o){ smn[t] = fminf(smn[t], smn[t+o]); smx[t] = fmaxf(smx[t], smx[t+o]); }
        __syncthreads();
    }
    if (t == 0){ g_qmm[2] = smn[0]; g_qmm[3] = smx[0]; }
}

/* ---- fc1: (bn2+relu+quant on load) 400->128, relu, minmax ---- */
__global__ void k_fc1(const int* __restrict__ qb){
    __shared__ float As[32][17];
    __shared__ float Bs[16][132];
    __shared__ unsigned smn, smx;
    int t = threadIdx.x;
    if (t == 0){ smn = 0xFFFFFFFFu; smx = 0u; }
    int rblk = blockIdx.x * 32;
    float lv = (float)((1 << qb[0]) - 1);
    float qs = (g_qmm[3] - g_qmm[2]) / lv;
    float rq = 1.0f / qs;
    float acc[4][4];
    #pragma unroll
    for (int i = 0; i < 4; i++)
        #pragma unroll
        for (int j = 0; j < 4; j++) acc[i][j] = 0.f;
    int rg = (t >> 5) * 4, c0 = t & 31;
    for (int kt = 0; kt < 400; kt += 16){
        for (int i = t; i < 512; i += 256){
            int row = i >> 4, kk = i & 15, k = kt + kk;
            int c = k / 25, rem = k % 25;
            float v = g_p2[((rblk + row)*16 + c)*25 + rem];
            float y = fmaxf(__fmul_rn(__fsub_rn(v, g_bn2m[c]), g_bn2i[c]), 0.f);
            As[row][kk] = fminf(fmaxf(rintf(y*rq), 0.f), lv) * qs;
        }
        for (int i = t; i < 2048; i += 256){
            int kk = i >> 7, nn = i & 127;
            Bs[kk][nn] = g_w3t[(kt + kk)*128 + nn];
        }
        __syncthreads();
        #pragma unroll
        for (int kk = 0; kk < 16; kk++){
            float a0 = As[rg][kk], a1 = As[rg+1][kk], a2 = As[rg+2][kk], a3 = As[rg+3][kk];
            float b0 = Bs[kk][c0], b1 = Bs[kk][c0+32], b2 = Bs[kk][c0+64], b3 = Bs[kk][c0+96];
            acc[0][0]=fmaf(a0,b0,acc[0][0]); acc[0][1]=fmaf(a0,b1,acc[0][1]);
            acc[0][2]=fmaf(a0,b2,acc[0][2]); acc[0][3]=fmaf(a0,b3,acc[0][3]);
            acc[1][0]=fmaf(a1,b0,acc[1][0]); acc[1][1]=fmaf(a1,b1,acc[1][1]);
            acc[1][2]=fmaf(a1,b2,acc[1][2]); acc[1][3]=fmaf(a1,b3,acc[1][3]);
            acc[2][0]=fmaf(a2,b0,acc[2][0]); acc[2][1]=fmaf(a2,b1,acc[2][1]);
            acc[2][2]=fmaf(a2,b2,acc[2][2]); acc[2][3]=fmaf(a2,b3,acc[2][3]);
            acc[3][0]=fmaf(a3,b0,acc[3][0]); acc[3][1]=fmaf(a3,b1,acc[3][1]);
            acc[3][2]=fmaf(a3,b2,acc[3][2]); acc[3][3]=fmaf(a3,b3,acc[3][3]);
        }
        __syncthreads();
    }
    float inv = g_inv[2];
    unsigned lmn = 0xFFFFFFFFu, lmx = 0u;
    #pragma unroll
    for (int ii = 0; ii < 4; ii++)
        #pragma unroll
        for (int jj = 0; jj < 4; jj++){
            float y = fmaxf(acc[ii][jj] * inv, 0.f);
            g_y3[(rblk + rg + ii)*128 + c0 + 32*jj] = y;
            unsigned e = fenc(y);
            lmn = min(lmn, e); lmx = max(lmx, e);
        }
    atomicMin(&smn, lmn); atomicMax(&smx, lmx);
    __syncthreads();
    if (t == 0){ atomicMin(&g_mm[6], smn); atomicMax(&g_mm[7], smx); }
}

/* ---- fc2 (quant on load) + log_softmax ---- */
__global__ void k_fc2(const int* __restrict__ qb, float* __restrict__ out){
    __shared__ float ws[1280];
    int t = threadIdx.x;
    for (int i = t; i < 1280; i += 256) ws[i] = g_w4[i];
    __syncthreads();
    float mn = fdec(g_mm[6]), mx = fdec(g_mm[7]);
    float lv = (float)((1 << qb[0]) - 1);
    float qs = (mx - mn) / lv;
    float rq = 1.0f / qs;
    float inv = g_inv[3];
    int warp = t / 32, lane = t % 32;
    int b = blockIdx.x * 8 + warp;
    float acc[10];
    #pragma unroll
    for (int o = 0; o < 10; o++) acc[o] = 0.f;
    for (int k = lane; k < 128; k += 32){
        float y = g_y3[b*128 + k];
        float q = fminf(fmaxf(rintf(y*rq), 0.f), lv) * qs;
        #pragma unroll
        for (int o = 0; o < 10; o++) acc[o] = fmaf(q, ws[o*128 + k], acc[o]);
    }
    #pragma unroll
    for (int off = 16; off > 0; off >>= 1)
        #pragma unroll
        for (int o = 0; o < 10; o++) acc[o] += __shfl_down_sync(0xFFFFFFFFu, acc[o], off);
    if (lane == 0){
        float l[10], m = -1e30f;
        #pragma unroll
        for (int o = 0; o < 10; o++){ l[o] = acc[o] * inv; m = fmaxf(m, l[o]); }
        float s = 0.f;
        #pragma unroll
        for (int o = 0; o < 10; o++) s += expf(l[o] - m);
        float ls = logf(s);
        #pragma unroll
        for (int o = 0; o < 10; o++) out[b*10 + o] = l[o] - m - ls;
    }
}

extern "C" void kernel_launch(void* const* d_in, const int* in_sizes, int n_in,
                              void* d_out, int out_size)
{
    const float* x   = (const float*)d_in[0];
    const float* sc1 = (const float*)d_in[1];
    const float* sg1 = (const float*)d_in[2];
    const float* h11 = (const float*)d_in[3];
    const float* h10 = (const float*)d_in[4];
    const float* sc2 = (const float*)d_in[5];
    const float* sg2 = (const float*)d_in[6];
    const float* h21 = (const float*)d_in[7];
    const float* h20 = (const float*)d_in[8];
    const float* sc3 = (const float*)d_in[9];
    const float* sg3 = (const float*)d_in[10];
    const float* h31 = (const float*)d_in[11];
    const float* h30 = (const float*)d_in[12];
    const float* sc4 = (const float*)d_in[13];
    const float* sg4 = (const float*)d_in[14];
    const float* h41 = (const float*)d_in[15];
    const float* h40 = (const float*)d_in[16];
    const int*   qb  = (const int*)d_in[17];
    float* out = (float*)d_out;

    cudaFuncSetAttribute(k_conv2, cudaFuncAttributeMaxDynamicSharedMemorySize, 189824);

    k_init<<<1, 128>>>();
    k_pool0<<<1568, 256>>>(x);
    k_wgen4<<<4, 1024>>>(sc1, sg1, h11, h10,
                         sc2, sg2, h21, h20,
                         sc3, sg3, h31, h30,
                         sc4, sg4, h41, h40);
    k_conv1s<<<1024, 256>>>(qb);
    k_fin1<<<64, 256>>>();
    k_q1<<<1, 64>>>();
    k_conv2<<<1024, 320, 189824>>>(qb);
    k_fin2<<<16, 256>>>();
    k_q2<<<1, 16>>>();
    k_fc1<<<128, 256>>>(qb);
    k_fc2<<<512, 256>>>(qb, out);
}